// round 12
// baseline (speedup 1.0000x reference)
#include <cuda_runtime.h>
#include <cstdint>

#define B  64
#define L  512
#define HB 768
#define HC 1024
#define H  (HB + HC)   // 1792
#define NL 7
#define NCH (H / 128)  // 14 chunks of 128 floats
#define BCH (HB / 128) // 6 bert chunks
#define NPP 3          // packed logit pairs (n0n1, n2n3, n4n5); n6 scalar
#define SWP_STRIDE (H * 8)                      // bytes per pair plane
#define SM6_OFF    (NPP * SWP_STRIDE)           // scalar w6 plane offset
#define SMEM_BYTES (SM6_OFF + H * 4)            // 50176

// Scratch (no allocations allowed).
__device__ int g_idx[B * L];
__device__ int g_count[B];
__device__ int g_ticket;

// ---------------------------------------------------------------------------
// Kernel 1: per-batch-row stable compaction via warp ballot scan.
// Also resets the work-queue ticket for kernel 2 (stream-ordered).
// ---------------------------------------------------------------------------
__global__ void build_idx_kernel(const int* __restrict__ valid) {
    int b    = blockIdx.x;
    int lane = threadIdx.x;
    if (b == 0 && lane == 0) g_ticket = 0;
    int base = b * L;

    int v[L / 32];
#pragma unroll
    for (int k = 0; k < L / 32; k++)
        v[k] = valid[base + k * 32 + lane];

    int count = 0;
#pragma unroll
    for (int k = 0; k < L / 32; k++) {
        unsigned m = __ballot_sync(0xffffffffu, v[k] != 0);
        if (v[k]) {
            int pos = count + __popc(m & ((1u << lane) - 1u));
            g_idx[base + pos] = k * 32 + lane;
        }
        count += __popc(m);
    }
    if (lane == 0) g_count[b] = count;
}

// ---------------------------------------------------------------------------
// Helpers.
// ---------------------------------------------------------------------------
__device__ __forceinline__ void ffma2(unsigned long long& d,
                                      unsigned long long a,
                                      unsigned long long b) {
    asm("fma.rn.f32x2 %0, %1, %2, %0;" : "+l"(d) : "l"(a), "l"(b));
}

__device__ __forceinline__ unsigned long long splat2(float x) {
    unsigned long long r;
    asm("mov.b64 %0, {%1, %1};" : "=l"(r) : "f"(x));
    return r;
}

__device__ __forceinline__ unsigned long long pack2(float lo, float hi) {
    unsigned long long r;
    asm("mov.b64 %0, {%1, %2};" : "=l"(r) : "f"(lo), "f"(hi));
    return r;
}

// XOR swizzle for the pair planes (lane stride 32 B): conflict-free LDS.128.
__device__ __forceinline__ uint32_t swz(uint32_t raw) {
    return raw ^ (((raw >> 7) & 3u) << 4);
}

// ---------------------------------------------------------------------------
// Kernel 2 config: TG=4 tokens/warp, 24 warps/SM (3 blocks x 256).
// ---------------------------------------------------------------------------
#define TPB 256
#define TG  4
#define NGROUPS ((B * L) / TG)   // 8192

struct AccT {
    unsigned long long p[TG][NPP];  // logit pairs (n0n1, n2n3, n4n5)
    float              s6[TG];      // logit n6 (scalar)
};

// One 128-float chunk: 6 swizzled pair LDS.128 + 1 scalar-plane LDS.128
// + 16 splats + 48 FFMA2 + 16 FFMA across 4 tokens.
__device__ __forceinline__ void compute_chunk(
    int c, const float4* xv, AccT& A,
    const unsigned char* sm, int lane)
{
    uint32_t hraw = (uint32_t)(c * 1024 + lane * 32);
    uint32_t oA = swz(hraw);
    uint32_t oB = swz(hraw + 16);

    ulonglong2 wA[NPP], wB[NPP];
#pragma unroll
    for (int np = 0; np < NPP; np++) {
        const unsigned char* p = sm + np * SWP_STRIDE;
        wA[np] = *reinterpret_cast<const ulonglong2*>(p + oA);  // pairs h, h+1
        wB[np] = *reinterpret_cast<const ulonglong2*>(p + oB);  // pairs h+2, h+3
    }
    // Scalar w6 plane: 16 B/lane, naturally conflict-free, no swizzle.
    float4 w6 = *reinterpret_cast<const float4*>(
        sm + SM6_OFF + (uint32_t)(c * 512 + lane * 16));

#pragma unroll
    for (int t = 0; t < TG; t++) {
        unsigned long long xs0 = splat2(xv[t].x);
        unsigned long long xs1 = splat2(xv[t].y);
        unsigned long long xs2 = splat2(xv[t].z);
        unsigned long long xs3 = splat2(xv[t].w);
#pragma unroll
        for (int np = 0; np < NPP; np++) {
            ffma2(A.p[t][np], xs0, wA[np].x);
            ffma2(A.p[t][np], xs1, wA[np].y);
            ffma2(A.p[t][np], xs2, wB[np].x);
            ffma2(A.p[t][np], xs3, wB[np].y);
        }
        A.s6[t] += xv[t].x * w6.x + xv[t].y * w6.y
                 + xv[t].z * w6.z + xv[t].w * w6.w;
    }
}

__global__ __launch_bounds__(TPB, 3) void tag_kernel(
    const float* __restrict__ bert,
    const float* __restrict__ comet,
    const float* __restrict__ w,      // [H, NL] row-major
    const float* __restrict__ bias,   // [NL]
    float* __restrict__ out)          // [B, L, NL]
{
    extern __shared__ unsigned char sm[];

    // Pair planes 0..2: {w[h][2np], w[h][2np+1]} at swizzled offset h*8.
    // Decomposition h = i/NPP covers ALL of [0,H); np = i%NPP.
    for (int i = threadIdx.x; i < NPP * H; i += TPB) {
        int h  = i / NPP;
        int np = i - h * NPP;
        *reinterpret_cast<unsigned long long*>(
            sm + np * SWP_STRIDE + swz((uint32_t)(h * 8))) =
            pack2(w[h * NL + 2 * np], w[h * NL + 2 * np + 1]);
    }
    // Scalar plane: w[h][6] at offset h*4.
    for (int h = threadIdx.x; h < H; h += TPB)
        *reinterpret_cast<float*>(sm + SM6_OFF + h * 4) = w[h * NL + 6];
    __syncthreads();

    int lane = threadIdx.x & 31;
    float bias_r = (lane < NL) ? bias[lane] : 0.0f;
    int hb = lane * 4;

    const float4 zero4 = make_float4(0.0f, 0.0f, 0.0f, 0.0f);

    for (;;) {
        int g;
        if (lane == 0) g = atomicAdd(&g_ticket, 1);
        g = __shfl_sync(0xffffffffu, g, 0);
        if (g >= NGROUPS) break;

        int tok0 = g * TG;
        int b    = tok0 >> 9;          // / L
        int p0   = tok0 & (L - 1);
        int cnt  = g_count[b];
        // Compaction makes valid slots a PREFIX: tokens t < nb have bert data.
        int nb = cnt - p0;
        nb = nb < 0 ? 0 : (nb > TG ? TG : nb);

        int boff[TG];
#pragma unroll
        for (int t = 0; t < TG; t++) {
            int j   = (t < nb) ? g_idx[b * L + p0 + t] : 0;
            boff[t] = (b * L + j) * HB;
        }
        const float* crow0 = comet + (size_t)(b * L + p0) * HC;

        AccT A;
#pragma unroll
        for (int t = 0; t < TG; t++) {
#pragma unroll
            for (int np = 0; np < NPP; np++) A.p[t][np] = 0ull;
            A.s6[t] = 0.0f;
        }

        if (nb > 0) {
#pragma unroll
            for (int c = 0; c < NCH; c++) {
                float4 x[TG];
#pragma unroll
                for (int t = 0; t < TG; t++) {
                    if (c < BCH) {
                        x[t] = (t < nb)
                            ? *reinterpret_cast<const float4*>(
                                  bert + boff[t] + c * 128 + hb)
                            : zero4;
                    } else {
                        x[t] = *reinterpret_cast<const float4*>(
                            crow0 + t * HC + (c - BCH) * 128 + hb);
                    }
                }
                compute_chunk(c, x, A, sm, lane);
            }
        } else {
            // All-invalid group: bert contribution is exactly zero.
#pragma unroll
            for (int cc = 0; cc < NCH - BCH; cc++) {
                float4 x[TG];
#pragma unroll
                for (int t = 0; t < TG; t++)
                    x[t] = *reinterpret_cast<const float4*>(
                        crow0 + t * HC + cc * 128 + hb);
                compute_chunk(BCH + cc, x, A, sm, lane);
            }
        }

        // --- unpack pairs, butterfly reduce, lanes 0..6 write logits ---
#pragma unroll
        for (int t = 0; t < TG; t++) {
            float f[7];
#pragma unroll
            for (int np = 0; np < NPP; np++)
                asm("mov.b64 {%0, %1}, %2;"
                    : "=f"(f[2 * np]), "=f"(f[2 * np + 1]) : "l"(A.p[t][np]));
            f[6] = A.s6[t];
            float v = 0.0f;
#pragma unroll
            for (int n = 0; n < NL; n++) {
                float s = f[n];
                s += __shfl_xor_sync(0xffffffffu, s, 16);
                s += __shfl_xor_sync(0xffffffffu, s, 8);
                s += __shfl_xor_sync(0xffffffffu, s, 4);
                s += __shfl_xor_sync(0xffffffffu, s, 2);
                s += __shfl_xor_sync(0xffffffffu, s, 1);
                if (lane == n) v = s;
            }
            if (lane < NL)
                out[(size_t)(tok0 + t) * NL + lane] = v + bias_r;
        }
    }
}

// ---------------------------------------------------------------------------
extern "C" void kernel_launch(void* const* d_in, const int* in_sizes, int n_in,
                              void* d_out, int out_size) {
    const float* bert  = (const float*)d_in[0];
    const float* comet = (const float*)d_in[1];
    const int*   valid = (const int*)d_in[2];
    const float* w     = (const float*)d_in[3];
    const float* bias  = (const float*)d_in[4];
    float*       out   = (float*)d_out;

    build_idx_kernel<<<B, 32>>>(valid);

    cudaFuncSetAttribute(tag_kernel,
                         cudaFuncAttributeMaxDynamicSharedMemorySize, SMEM_BYTES);

    // 444 blocks = 3/SM (24 warps/SM), persistent; ticket queue balances
    // the 8192 groups across 3552 warps exactly.
    const int grid = 444;
    tag_kernel<<<grid, TPB, SMEM_BYTES>>>(bert, comet, w, bias, out);
}